// round 4
// baseline (speedup 1.0000x reference)
#include <cuda_runtime.h>
#include <math.h>

// Problem constants (fixed by setup_inputs)
#define WINC    20
#define OFFSETC 40
#define FDIM    8192
#define CDIM    256
#define PDIM    256
#define NBLK    1024           // = B*P/8 warps = B*SIL_CHUNKS  (B=32, P=256)

__device__ float g_part[NBLK];
__device__ unsigned int g_ticket = 0;

__device__ __forceinline__ float block_reduce_sum(float v) {
    __shared__ float sh[32];
    int lane = threadIdx.x & 31;
    int w    = threadIdx.x >> 5;
    #pragma unroll
    for (int o = 16; o; o >>= 1) v += __shfl_down_sync(0xffffffffu, v, o);
    if (lane == 0) sh[w] = v;
    __syncthreads();
    int nw = (blockDim.x + 31) >> 5;
    v = (threadIdx.x < nw) ? sh[threadIdx.x] : 0.0f;
    if (w == 0) {
        #pragma unroll
        for (int o = 16; o; o >>= 1) v += __shfl_down_sync(0xffffffffu, v, o);
    }
    return v;
}

// Single-wave fused kernel: 1024 blocks x 256 threads (8 blocks/SM x 148 SMs = 1184 capacity).
// Each block handles 8 phonemes (one per warp) AND one 256-frame silence chunk.
// Last block to finish does the deterministic final reduction.
__global__ void fused_kernel(const float* __restrict__ X,
                             const int* __restrict__ lengths,
                             const int* __restrict__ tgt,
                             const int* __restrict__ p_end,
                             const int* __restrict__ pnum,
                             float* __restrict__ out) {
    const unsigned FULL = 0xffffffffu;
    int bid  = blockIdx.x;
    int lane = threadIdx.x & 31;
    int wid  = threadIdx.x >> 5;

    float contrib = 0.0f;

    // ---------- silence term: block bid covers chunk (b = bid>>5, ch = bid&31) ----------
    {
        int b  = bid >> 5;                 // SIL_CHUNKS = 32
        int ch = bid & 31;
        int tf = ch * 256 + threadIdx.x;

        int len = lengths[b];
        int pn  = pnum[b];
        int ends_ph = min(p_end[b] + OFFSETC, len);
        int first_start = max(ends_ph - WINC * pn, 0);
        int sl = max(ends_ph - WINC, 0);
        int last_end = min(sl + WINC, len);

        // mask = (tf < first_start) | ((tf >= last_end) & (tf < len))
        if ((tf < first_start) || ((tf >= last_end) && (tf < len))) {
            contrib = -X[((size_t)b * FDIM + tf) * CDIM];   // SIL column = 0
        }
    }

    // ---------- phoneme term: warp (bid*8 + wid) handles one (b, p) ----------
    {
        int w = (bid << 3) + wid;          // global warp id in [0, B*P)
        int b = w >> 8;                    // P = 256
        int p = w & 255;
        int len = lengths[b];
        int pn  = pnum[b];

        if (p < pn) {
            int ends_ph = min(p_end[b] + OFFSETC, len);
            int start   = max(ends_ph - WINC * (pn - p), 0);
            int wlen    = min(start + WINC, len) - start;
            int c       = tgt[b * PDIM + p];

            float v = 0.0f;
            if (lane < WINC && lane < wlen) {
                int fi = min(start + lane, FDIM - 1);
                v = X[((size_t)b * FDIM + fi) * CDIM + c];
            }

            // Gaussian taps (float32, identical arithmetic to jnp reference)
            float g[9];
            float s = 0.0f;
            #pragma unroll
            for (int i = 0; i < 9; i++) {
                float x = (float)(i - 4) * 0.25f;
                g[i] = expf(-0.5f * x * x);
                s += g[i];
            }
            #pragma unroll
            for (int i = 0; i < 9; i++) g[i] = g[i] / s;

            // smoothed[lane] = sum_i g[i] * v[lane + i - 3]; out-of-range -> 0
            // (idx & 31 wraps negatives onto lanes 29..31 which hold v = 0,
            //  and idx in [20,24] hits zero lanes too)
            float sm = 0.0f;
            #pragma unroll
            for (int i = 0; i < 9; i++) {
                int idx = lane + i - 3;
                float vi = __shfl_sync(FULL, v, idx & 31);
                sm += g[i] * vi;
            }

            float m = (lane < wlen && lane < WINC) ? sm : -INFINITY;
            #pragma unroll
            for (int o = 16; o; o >>= 1) m = fmaxf(m, __shfl_xor_sync(FULL, m, o));
            if (lane == 0) contrib += -m;
        }
    }

    float tot = block_reduce_sum(contrib);

    // ---------- last-block-done deterministic final reduction ----------
    __shared__ bool is_last;
    if (threadIdx.x == 0) {
        g_part[bid] = tot;
        __threadfence();                   // fence only in warp 0's predicated path
        unsigned t = atomicAdd(&g_ticket, 1u);
        is_last = (t == (unsigned)(NBLK - 1));
    }
    __syncthreads();   // also separates the two uses of block_reduce's smem

    if (is_last) {
        float v = 0.0f;
        for (int i = threadIdx.x; i < NBLK; i += blockDim.x) v += g_part[i];
        float total = block_reduce_sum(v);
        if (threadIdx.x == 0) {
            out[0] = total;
            g_ticket = 0;    // reset for the next graph replay
        }
    }
}

extern "C" void kernel_launch(void* const* d_in, const int* in_sizes, int n_in,
                              void* d_out, int out_size) {
    const float* X       = (const float*)d_in[0];
    const int*   lengths = (const int*)d_in[1];
    const int*   tgt     = (const int*)d_in[2];
    const int*   p_end   = (const int*)d_in[3];
    const int*   pnum    = (const int*)d_in[4];
    float*       out     = (float*)d_out;

    fused_kernel<<<NBLK, 256>>>(X, lengths, tgt, p_end, pnum, out);
}

// round 5
// speedup vs baseline: 1.1860x; 1.1860x over previous
#include <cuda_runtime.h>
#include <math.h>

// Problem constants (fixed by setup_inputs)
#define WINC    20
#define OFFSETC 40
#define FDIM    8192
#define CDIM    256
#define PDIM    256
#define NBLK    256            // 256 blocks x 1024 threads = B*F threads = 8*B*P warps
#define NTHR    1024

__device__ float g_part[NBLK];
__device__ unsigned int g_ticket = 0;

__device__ __forceinline__ float block_reduce_sum(float v) {
    __shared__ float sh[32];
    int lane = threadIdx.x & 31;
    int w    = threadIdx.x >> 5;
    #pragma unroll
    for (int o = 16; o; o >>= 1) v += __shfl_down_sync(0xffffffffu, v, o);
    if (lane == 0) sh[w] = v;
    __syncthreads();
    int nw = blockDim.x >> 5;
    v = (threadIdx.x < nw) ? sh[threadIdx.x] : 0.0f;
    if (w == 0) {
        #pragma unroll
        for (int o = 16; o; o >>= 1) v += __shfl_down_sync(0xffffffffu, v, o);
    }
    return v;
}

// Single kernel, 256 blocks x 1024 threads (2 blocks/SM, one wave).
// Thread gt in [0, B*F): silence frame (b = gt>>13, tf = gt&8191).
// Warp  w  in [0, B*P): phoneme (b = w>>8, p = w&255).
// Last block (acq_rel ticket) does the deterministic final reduction.
__global__ void __launch_bounds__(NTHR, 2)
fused_kernel(const float* __restrict__ X,
             const int* __restrict__ lengths,
             const int* __restrict__ tgt,
             const int* __restrict__ p_end,
             const int* __restrict__ pnum,
             float* __restrict__ out) {
    const unsigned FULL = 0xffffffffu;
    int bid  = blockIdx.x;
    int lane = threadIdx.x & 31;

    float contrib = 0.0f;

    // ---------- silence term: one frame per thread ----------
    {
        int gt = bid * NTHR + threadIdx.x;     // [0, B*F)
        int b  = gt >> 13;                     // F = 8192
        int tf = gt & 8191;

        int len = lengths[b];
        int pn  = pnum[b];
        int ends_ph = min(p_end[b] + OFFSETC, len);
        int first_start = max(ends_ph - WINC * pn, 0);
        int sl = max(ends_ph - WINC, 0);
        int last_end = min(sl + WINC, len);

        // mask = (tf < first_start) | ((tf >= last_end) & (tf < len))
        if ((tf < first_start) || ((tf >= last_end) && (tf < len))) {
            contrib = -X[((size_t)b * FDIM + tf) * CDIM];   // SIL column = 0
        }
    }

    // ---------- phoneme term: one (b, p) per warp ----------
    {
        int w = (bid << 5) + (threadIdx.x >> 5);  // global warp id in [0, B*P)
        int b = w >> 8;                           // P = 256
        int p = w & 255;
        int len = lengths[b];
        int pn  = pnum[b];

        if (p < pn) {
            int ends_ph = min(p_end[b] + OFFSETC, len);
            int start   = max(ends_ph - WINC * (pn - p), 0);
            int wlen    = min(start + WINC, len) - start;
            int c       = tgt[b * PDIM + p];

            float v = 0.0f;
            if (lane < WINC && lane < wlen) {
                int fi = min(start + lane, FDIM - 1);
                v = X[((size_t)b * FDIM + fi) * CDIM + c];
            }

            // Gaussian taps (float32, identical arithmetic to jnp reference)
            float g[9];
            float s = 0.0f;
            #pragma unroll
            for (int i = 0; i < 9; i++) {
                float x = (float)(i - 4) * 0.25f;
                g[i] = expf(-0.5f * x * x);
                s += g[i];
            }
            #pragma unroll
            for (int i = 0; i < 9; i++) g[i] = g[i] / s;

            // smoothed[lane] = sum_i g[i] * v[lane + i - 3]; out-of-range -> 0
            float sm = 0.0f;
            #pragma unroll
            for (int i = 0; i < 9; i++) {
                int idx = lane + i - 3;
                float vi = __shfl_sync(FULL, v, idx & 31);
                sm += g[i] * vi;
            }

            float m = (lane < wlen && lane < WINC) ? sm : -INFINITY;
            #pragma unroll
            for (int o = 16; o; o >>= 1) m = fmaxf(m, __shfl_xor_sync(FULL, m, o));
            if (lane == 0) contrib += -m;
        }
    }

    float tot = block_reduce_sum(contrib);

    // ---------- last-block-done final reduction (acq_rel ticket, no membar) ----------
    __shared__ bool is_last;
    if (threadIdx.x == 0) {
        g_part[bid] = tot;                       // STG is write-through to L2
        unsigned t;
        // release: orders the partial store before the ticket increment;
        // acquire: makes all released partials visible to the winner.
        asm volatile("atom.add.acq_rel.gpu.global.u32 %0, [%1], %2;"
                     : "=r"(t) : "l"(&g_ticket), "r"(1u) : "memory");
        is_last = (t == (unsigned)(NBLK - 1));
    }
    __syncthreads();   // also separates the two uses of block_reduce's smem

    if (is_last) {
        float v = 0.0f;
        if (threadIdx.x < NBLK) {
            // L2 read (bypass L1): partials were released to L2 by producers
            v = __ldcg(&g_part[threadIdx.x]);
        }
        float total = block_reduce_sum(v);
        if (threadIdx.x == 0) {
            out[0] = total;
            g_ticket = 0;    // reset for the next graph replay
        }
    }
}

extern "C" void kernel_launch(void* const* d_in, const int* in_sizes, int n_in,
                              void* d_out, int out_size) {
    const float* X       = (const float*)d_in[0];
    const int*   lengths = (const int*)d_in[1];
    const int*   tgt     = (const int*)d_in[2];
    const int*   p_end   = (const int*)d_in[3];
    const int*   pnum    = (const int*)d_in[4];
    float*       out     = (float*)d_out;

    fused_kernel<<<NBLK, NTHR>>>(X, lengths, tgt, p_end, pnum, out);
}

// round 6
// speedup vs baseline: 1.1895x; 1.0029x over previous
#include <cuda_runtime.h>
#include <math.h>

// Problem constants (fixed by setup_inputs)
#define WINC    20
#define OFFSETC 40
#define FDIM    8192
#define CDIM    256
#define PDIM    256
#define NBLK    256            // 8 blocks per batch (B=32)
#define NTHR    1024

__device__ float g_part[NBLK];
__device__ unsigned int g_ticket = 0;

__device__ __forceinline__ float block_reduce_sum(float v) {
    __shared__ float sh[32];
    int lane = threadIdx.x & 31;
    int w    = threadIdx.x >> 5;
    #pragma unroll
    for (int o = 16; o; o >>= 1) v += __shfl_down_sync(0xffffffffu, v, o);
    if (lane == 0) sh[w] = v;
    __syncthreads();
    int nw = blockDim.x >> 5;
    v = (threadIdx.x < nw) ? sh[threadIdx.x] : 0.0f;
    if (w == 0) {
        #pragma unroll
        for (int o = 16; o; o >>= 1) v += __shfl_down_sync(0xffffffffu, v, o);
    }
    return v;
}

// Per-warp phoneme evaluation: given lane value v (smoothing input), wlen,
// returns -max(smoothed) on lane 0, 0 elsewhere. g[] = Gaussian taps.
__device__ __forceinline__ float phoneme_eval(float v, int wlen, const float* g,
                                              int lane) {
    const unsigned FULL = 0xffffffffu;
    float sm = 0.0f;
    #pragma unroll
    for (int i = 0; i < 9; i++) {
        int idx = lane + i - 3;
        float vi = __shfl_sync(FULL, v, idx & 31);  // wraps onto zero lanes
        sm += g[i] * vi;
    }
    float m = (lane < wlen && lane < WINC) ? sm : -INFINITY;
    #pragma unroll
    for (int o = 16; o; o >>= 1) m = fmaxf(m, __shfl_xor_sync(FULL, m, o));
    return (lane == 0) ? -m : 0.0f;
}

// Single-wave kernel: 256 blocks x 1024 threads (2 blocks/SM).
// Block bid -> batch b = bid>>3, sub-chunk sub = bid&7.
//  threads [0,512):  silence, 2 frames each: tf = sub*1024 + t (+512)
//  warps  [16,32):   phonemes, 2 per warp: p = sub*32 + wi (+16)
__global__ void __launch_bounds__(NTHR, 2)
fused_kernel(const float* __restrict__ X,
             const int* __restrict__ lengths,
             const int* __restrict__ tgt,
             const int* __restrict__ p_end,
             const int* __restrict__ pnum,
             float* __restrict__ out) {
    int bid  = blockIdx.x;
    int tid  = threadIdx.x;
    int lane = tid & 31;
    int b    = bid >> 3;
    int sub  = bid & 7;

    // Uniform per-block batch metadata (broadcast loads)
    int len = lengths[b];
    int pn  = pnum[b];
    int ends_ph = min(p_end[b] + OFFSETC, len);

    float contrib = 0.0f;

    if (tid < 512) {
        // ---------- silence: 2 independent frames per thread ----------
        int first_start = max(ends_ph - WINC * pn, 0);
        int last_end    = min(max(ends_ph - WINC, 0) + WINC, len);

        int tf1 = (sub << 10) + tid;
        int tf2 = tf1 + 512;
        const float* xp = X + (size_t)b * FDIM * CDIM;

        bool m1 = (tf1 < first_start) || ((tf1 >= last_end) && (tf1 < len));
        bool m2 = (tf2 < first_start) || ((tf2 >= last_end) && (tf2 < len));
        float v1 = 0.0f, v2 = 0.0f;
        if (m1) v1 = xp[(size_t)tf1 * CDIM];   // SIL column = 0
        if (m2) v2 = xp[(size_t)tf2 * CDIM];
        contrib = -v1 - v2;
    } else {
        // ---------- phonemes: 2 per warp ----------
        int wi = (tid - 512) >> 5;            // [0,16)
        int p1 = (sub << 5) + wi;
        int p2 = p1 + 16;
        const float* xp = X + (size_t)b * FDIM * CDIM;

        // target columns (uniform per warp, tgt row stays hot in L2)
        int c1 = tgt[b * PDIM + p1];
        int c2 = tgt[b * PDIM + p2];

        int start1 = max(ends_ph - WINC * (pn - p1), 0);
        int start2 = max(ends_ph - WINC * (pn - p2), 0);
        int wlen1  = min(start1 + WINC, len) - start1;
        int wlen2  = min(start2 + WINC, len) - start2;

        // front-batch both 20-lane gathers
        float v1 = 0.0f, v2 = 0.0f;
        bool a1 = (p1 < pn) && (lane < WINC) && (lane < wlen1);
        bool a2 = (p2 < pn) && (lane < WINC) && (lane < wlen2);
        if (a1) v1 = xp[(size_t)min(start1 + lane, FDIM - 1) * CDIM + c1];
        if (a2) v2 = xp[(size_t)min(start2 + lane, FDIM - 1) * CDIM + c2];

        // Gaussian taps (float32, identical arithmetic to jnp reference)
        float g[9];
        float s = 0.0f;
        #pragma unroll
        for (int i = 0; i < 9; i++) {
            float x = (float)(i - 4) * 0.25f;
            g[i] = expf(-0.5f * x * x);
            s += g[i];
        }
        #pragma unroll
        for (int i = 0; i < 9; i++) g[i] = g[i] / s;

        if (p1 < pn) contrib += phoneme_eval(v1, wlen1, g, lane);
        if (p2 < pn) contrib += phoneme_eval(v2, wlen2, g, lane);
    }

    float tot = block_reduce_sum(contrib);

    // ---------- last-block-done final reduction (acq_rel ticket) ----------
    __shared__ bool is_last;
    if (tid == 0) {
        g_part[bid] = tot;
        unsigned t;
        asm volatile("atom.add.acq_rel.gpu.global.u32 %0, [%1], %2;"
                     : "=r"(t) : "l"(&g_ticket), "r"(1u) : "memory");
        is_last = (t == (unsigned)(NBLK - 1));
    }
    __syncthreads();

    if (is_last) {
        float v = 0.0f;
        if (tid < NBLK) v = __ldcg(&g_part[tid]);
        float total = block_reduce_sum(v);
        if (tid == 0) {
            out[0] = total;
            g_ticket = 0;    // reset for the next graph replay
        }
    }
}

extern "C" void kernel_launch(void* const* d_in, const int* in_sizes, int n_in,
                              void* d_out, int out_size) {
    const float* X       = (const float*)d_in[0];
    const int*   lengths = (const int*)d_in[1];
    const int*   tgt     = (const int*)d_in[2];
    const int*   p_end   = (const int*)d_in[3];
    const int*   pnum    = (const int*)d_in[4];
    float*       out     = (float*)d_out;

    fused_kernel<<<NBLK, NTHR>>>(X, lengths, tgt, p_end, pnum, out);
}

// round 8
// speedup vs baseline: 1.2179x; 1.0239x over previous
#include <cuda_runtime.h>
#include <cstdint>
#include <math.h>

// Problem constants (fixed by setup_inputs)
#define WINC    20
#define OFFSETC 40
#define FDIM    8192
#define CDIM    256
#define PDIM    256
#define NBLK    256            // 8 blocks per batch (B=32)
#define NTHR    1024

__device__ float g_part[NBLK];
__device__ unsigned int g_ticket = 0;

__device__ __forceinline__ float block_reduce_sum(float v) {
    __shared__ float sh[32];
    int lane = threadIdx.x & 31;
    int w    = threadIdx.x >> 5;
    #pragma unroll
    for (int o = 16; o; o >>= 1) v += __shfl_down_sync(0xffffffffu, v, o);
    if (lane == 0) sh[w] = v;
    __syncthreads();
    int nw = blockDim.x >> 5;
    v = (threadIdx.x < nw) ? sh[threadIdx.x] : 0.0f;
    if (w == 0) {
        #pragma unroll
        for (int o = 16; o; o >>= 1) v += __shfl_down_sync(0xffffffffu, v, o);
    }
    return v;
}

__device__ __forceinline__ void cp_async_4(unsigned int smem_addr,
                                           const void* gptr, int src_size) {
    // zero-fills the 4-byte dst when src_size == 0 (no global read issued)
    asm volatile("cp.async.ca.shared.global [%0], [%1], 4, %2;"
                 :: "r"(smem_addr), "l"(gptr), "r"(src_size));
}

__device__ __forceinline__ unsigned int smem_u32(const void* p) {
    unsigned int a;
    asm("{ .reg .u64 t; cvta.to.shared.u64 t, %1; cvt.u32.u64 %0, t; }"
        : "=r"(a) : "l"(p));
    return a;
}

// Single-wave kernel: 256 blocks x 1024 threads (2 blocks/SM).
// Block bid -> batch b = bid>>3, sub-chunk sub = bid&7.
//  sil:      frame tf = sub*1024 + tid, one cp.async per thread
//  phoneme:  32 phonemes (p = sub*32 + [0,32)), 20 taps each, filled by
//            threads 0..639 (one cp.async each), evaluated warp wid -> phoneme wid.
__global__ void __launch_bounds__(NTHR, 2)
fused_kernel(const float* __restrict__ X,
             const int* __restrict__ lengths,
             const int* __restrict__ tgt,
             const int* __restrict__ p_end,
             const int* __restrict__ pnum,
             float* __restrict__ out) {
    __shared__ float s_sil[NTHR];        // 4 KB
    __shared__ float s_ph[32 * WINC];    // 2.5 KB

    const unsigned FULL = 0xffffffffu;
    int bid  = blockIdx.x;
    int tid  = threadIdx.x;
    int lane = tid & 31;
    int wid  = tid >> 5;
    int b    = bid >> 3;
    int sub  = bid & 7;

    // Uniform per-block batch metadata (broadcast loads)
    int len = lengths[b];
    int pn  = pnum[b];
    int ends_ph = min(p_end[b] + OFFSETC, len);
    const float* xp = X + (size_t)b * FDIM * CDIM;

    unsigned int s_sil_base = smem_u32(s_sil);
    unsigned int s_ph_base  = smem_u32(s_ph);

    // ---------- issue silence gather (1 cp.async per thread) ----------
    int first_start = max(ends_ph - WINC * pn, 0);
    int last_end    = min(max(ends_ph - WINC, 0) + WINC, len);
    {
        int tf = (sub << 10) + tid;
        // mask = (tf < first_start) | ((tf >= last_end) & (tf < len))
        bool m = (tf < first_start) || ((tf >= last_end) && (tf < len));
        cp_async_4(s_sil_base + tid * 4, xp + (size_t)tf * CDIM, m ? 4 : 0);
    }

    // ---------- issue phoneme gather (threads 0..639, 1 cp.async each) ----------
    if (tid < 32 * WINC) {
        int lp = tid / WINC;               // local phoneme [0,32)
        int k  = tid - lp * WINC;          // tap [0,20)
        int p  = (sub << 5) + lp;
        int start = max(ends_ph - WINC * (pn - p), 0);
        int wlen  = min(start + WINC, len) - start;
        bool m = (p < pn) && (k < wlen);
        int c  = tgt[b * PDIM + p];
        int fi = min(start + k, FDIM - 1);
        cp_async_4(s_ph_base + tid * 4, xp + (size_t)fi * CDIM + c, m ? 4 : 0);
    }
    asm volatile("cp.async.commit_group;");

    // ---------- Gaussian taps while copies are in flight ----------
    float g[9];
    {
        float s = 0.0f;
        #pragma unroll
        for (int i = 0; i < 9; i++) {
            float x = (float)(i - 4) * 0.25f;
            g[i] = __expf(-0.5f * x * x);
            s += g[i];
        }
        float si = 1.0f / s;
        #pragma unroll
        for (int i = 0; i < 9; i++) g[i] *= si;
    }

    asm volatile("cp.async.wait_group 0;");
    __syncthreads();

    // ---------- compute ----------
    float contrib = -s_sil[tid];           // masked slots were zero-filled

    {
        int p = (sub << 5) + wid;          // warp wid -> phoneme p
        if (p < pn) {
            int start = max(ends_ph - WINC * (pn - p), 0);
            int wlen  = min(start + WINC, len) - start;

            float v = (lane < WINC) ? s_ph[wid * WINC + lane] : 0.0f;

            // smoothed[lane] = sum_i g[i] * v[lane + i - 3]; out-of-range -> 0
            float sm = 0.0f;
            #pragma unroll
            for (int i = 0; i < 9; i++) {
                int idx = lane + i - 3;
                float vi = __shfl_sync(FULL, v, idx & 31);  // wraps onto zero lanes
                sm += g[i] * vi;
            }

            float m = (lane < wlen && lane < WINC) ? sm : -INFINITY;
            #pragma unroll
            for (int o = 16; o; o >>= 1) m = fmaxf(m, __shfl_xor_sync(FULL, m, o));
            if (lane == 0) contrib += -m;
        }
    }

    float tot = block_reduce_sum(contrib);

    // ---------- last-block-done final reduction (acq_rel ticket) ----------
    __shared__ bool is_last;
    if (tid == 0) {
        g_part[bid] = tot;
        unsigned int t;
        asm volatile("atom.add.acq_rel.gpu.global.u32 %0, [%1], %2;"
                     : "=r"(t) : "l"(&g_ticket), "r"(1u) : "memory");
        is_last = (t == (unsigned int)(NBLK - 1));
    }
    __syncthreads();

    if (is_last) {
        float v = 0.0f;
        if (tid < NBLK) v = __ldcg(&g_part[tid]);
        float total = block_reduce_sum(v);
        if (tid == 0) {
            out[0] = total;
            g_ticket = 0;    // reset for the next graph replay
        }
    }
}

extern "C" void kernel_launch(void* const* d_in, const int* in_sizes, int n_in,
                              void* d_out, int out_size) {
    const float* X       = (const float*)d_in[0];
    const int*   lengths = (const int*)d_in[1];
    const int*   tgt     = (const int*)d_in[2];
    const int*   p_end   = (const int*)d_in[3];
    const int*   pnum    = (const int*)d_in[4];
    float*       out     = (float*)d_out;

    fused_kernel<<<NBLK, NTHR>>>(X, lengths, tgt, p_end, pnum, out);
}

// round 9
// speedup vs baseline: 1.2952x; 1.0635x over previous
#include <cuda_runtime.h>
#include <cstdint>
#include <math.h>

// Problem constants (fixed by setup_inputs)
#define WINC    20
#define OFFSETC 40
#define FDIM    8192
#define CDIM    256
#define PDIM    256
#define NBLK    256            // 8 blocks per batch (B=32)
#define NTHR    1024

__device__ __forceinline__ float block_reduce_sum(float v) {
    __shared__ float sh[32];
    int lane = threadIdx.x & 31;
    int w    = threadIdx.x >> 5;
    #pragma unroll
    for (int o = 16; o; o >>= 1) v += __shfl_down_sync(0xffffffffu, v, o);
    if (lane == 0) sh[w] = v;
    __syncthreads();
    int nw = blockDim.x >> 5;
    v = (threadIdx.x < nw) ? sh[threadIdx.x] : 0.0f;
    if (w == 0) {
        #pragma unroll
        for (int o = 16; o; o >>= 1) v += __shfl_down_sync(0xffffffffu, v, o);
    }
    return v;
}

// Single-wave kernel: 256 blocks x 1024 threads (2 blocks/SM).
// Block bid -> batch b = bid>>3, sub-chunk sub = bid&7.
//  each thread: one silence frame;  each warp: one phoneme.
// Block partial goes straight to out[0] via RED.ADD.F32 (all terms >= 0,
// reorder error ~1e-7 << 1e-3 tolerance). out[0] zeroed by a memset node.
__global__ void __launch_bounds__(NTHR, 2)
fused_kernel(const float* __restrict__ X,
             const int* __restrict__ lengths,
             const int* __restrict__ tgt,
             const int* __restrict__ p_end,
             const int* __restrict__ pnum,
             float* __restrict__ out) {
    const unsigned FULL = 0xffffffffu;
    int bid  = blockIdx.x;
    int tid  = threadIdx.x;
    int lane = tid & 31;
    int wid  = tid >> 5;
    int b    = bid >> 3;
    int sub  = bid & 7;

    // Uniform per-block batch metadata (broadcast loads)
    int len = lengths[b];
    int pn  = pnum[b];
    int ends_ph = min(p_end[b] + OFFSETC, len);
    const float* xp = X + (size_t)b * FDIM * CDIM;

    float contrib = 0.0f;

    // ---------- silence term: one frame per thread ----------
    {
        int first_start = max(ends_ph - WINC * pn, 0);
        int last_end    = min(max(ends_ph - WINC, 0) + WINC, len);
        int tf = (sub << 10) + tid;
        // mask = (tf < first_start) | ((tf >= last_end) & (tf < len))
        if ((tf < first_start) || ((tf >= last_end) && (tf < len))) {
            contrib = -xp[(size_t)tf * CDIM];      // SIL column = 0
        }
    }

    // ---------- phoneme term: one (b, p) per warp ----------
    {
        int p = (sub << 5) + wid;
        if (p < pn) {
            int start = max(ends_ph - WINC * (pn - p), 0);
            int wlen  = min(start + WINC, len) - start;
            int c     = tgt[b * PDIM + p];

            float v = 0.0f;
            if (lane < WINC && lane < wlen) {
                int fi = min(start + lane, FDIM - 1);
                v = xp[(size_t)fi * CDIM + c];
            }

            // Gaussian taps (float32, identical arithmetic to jnp reference)
            float g[9];
            float s = 0.0f;
            #pragma unroll
            for (int i = 0; i < 9; i++) {
                float x = (float)(i - 4) * 0.25f;
                g[i] = expf(-0.5f * x * x);
                s += g[i];
            }
            #pragma unroll
            for (int i = 0; i < 9; i++) g[i] = g[i] / s;

            // smoothed[lane] = sum_i g[i] * v[lane + i - 3]; out-of-range -> 0
            // (idx & 31 wraps onto lanes >= 20 which hold v = 0)
            float sm = 0.0f;
            #pragma unroll
            for (int i = 0; i < 9; i++) {
                int idx = lane + i - 3;
                float vi = __shfl_sync(FULL, v, idx & 31);
                sm += g[i] * vi;
            }

            float m = (lane < wlen && lane < WINC) ? sm : -INFINITY;
            #pragma unroll
            for (int o = 16; o; o >>= 1) m = fmaxf(m, __shfl_xor_sync(FULL, m, o));
            if (lane == 0) contrib += -m;
        }
    }

    float tot = block_reduce_sum(contrib);
    if (tid == 0) atomicAdd(out, tot);     // RED.ADD.F32, no-return fast path
}

extern "C" void kernel_launch(void* const* d_in, const int* in_sizes, int n_in,
                              void* d_out, int out_size) {
    const float* X       = (const float*)d_in[0];
    const int*   lengths = (const int*)d_in[1];
    const int*   tgt     = (const int*)d_in[2];
    const int*   p_end   = (const int*)d_in[3];
    const int*   pnum    = (const int*)d_in[4];
    float*       out     = (float*)d_out;

    cudaMemsetAsync(out, 0, sizeof(float));          // graph-capturable memset node
    fused_kernel<<<NBLK, NTHR>>>(X, lengths, tgt, p_end, pnum, out);
}

// round 10
// speedup vs baseline: 1.3077x; 1.0096x over previous
#include <cuda_runtime.h>
#include <cstdint>
#include <math.h>

// Problem constants (fixed by setup_inputs)
#define WINC    20
#define OFFSETC 40
#define FDIM    8192
#define CDIM    256
#define PDIM    256
#define NBLK    256            // 8 blocks per batch (B=32)
#define NTHR    1024

// Gaussian taps g[i] = exp(-0.5*((i-4)/4)^2) / sum, precomputed to float32
// accuracy (matches the jnp float32 computation to ~1e-7 relative).
__device__ __constant__ const float G0 = 0.08167445f;
__device__ __constant__ const float G1 = 0.10164549f;
__device__ __constant__ const float G2 = 0.11883562f;
__device__ __constant__ const float G3 = 0.13051539f;
__device__ __constant__ const float G4 = 0.13465840f;

__device__ __forceinline__ float block_reduce_sum(float v) {
    __shared__ float sh[32];
    int lane = threadIdx.x & 31;
    int w    = threadIdx.x >> 5;
    #pragma unroll
    for (int o = 16; o; o >>= 1) v += __shfl_down_sync(0xffffffffu, v, o);
    if (lane == 0) sh[w] = v;
    __syncthreads();
    int nw = blockDim.x >> 5;
    v = (threadIdx.x < nw) ? sh[threadIdx.x] : 0.0f;
    if (w == 0) {
        #pragma unroll
        for (int o = 16; o; o >>= 1) v += __shfl_down_sync(0xffffffffu, v, o);
    }
    return v;
}

// Single-wave kernel: 256 blocks x 1024 threads (2 blocks/SM).
// Block bid -> batch b = bid>>3, sub-chunk sub = bid&7.
//  each thread: one silence frame;  each warp: one phoneme.
// Block partial -> RED.ADD.F32 into out[0] (all terms >= 0; reorder error ~1e-7).
__global__ void __launch_bounds__(NTHR, 2)
fused_kernel(const float* __restrict__ X,
             const int* __restrict__ lengths,
             const int* __restrict__ tgt,
             const int* __restrict__ p_end,
             const int* __restrict__ pnum,
             float* __restrict__ out) {
    const unsigned FULL = 0xffffffffu;
    int bid  = blockIdx.x;
    int tid  = threadIdx.x;
    int lane = tid & 31;
    int wid  = tid >> 5;
    int b    = bid >> 3;
    int sub  = bid & 7;

    // Uniform per-block batch metadata (broadcast loads)
    int len = __ldg(&lengths[b]);
    int pn  = __ldg(&pnum[b]);
    int ends_ph = min(__ldg(&p_end[b]) + OFFSETC, len);
    const float* xp = X + (size_t)b * FDIM * CDIM;

    // ---- phoneme setup: issue tgt load early so tgt->X chain overlaps sil ----
    int p = (sub << 5) + wid;              // warp wid -> phoneme p
    bool ph_act = (p < pn);
    int c = ph_act ? __ldg(&tgt[b * PDIM + p]) : 0;
    int start = max(ends_ph - WINC * (pn - p), 0);
    int wlen  = min(start + WINC, len) - start;

    float contrib = 0.0f;

    // ---------- silence term: one frame per thread ----------
    {
        int first_start = max(ends_ph - WINC * pn, 0);
        int last_end    = min(max(ends_ph - WINC, 0) + WINC, len);
        int tf = (sub << 10) + tid;
        // mask = (tf < first_start) | ((tf >= last_end) & (tf < len))
        if ((tf < first_start) || ((tf >= last_end) && (tf < len))) {
            contrib = -xp[(size_t)tf * CDIM];      // SIL column = 0
        }
    }

    // ---------- phoneme term: one (b, p) per warp ----------
    if (ph_act) {
        float v = 0.0f;
        if (lane < WINC && lane < wlen) {
            int fi = min(start + lane, FDIM - 1);
            v = xp[(size_t)fi * CDIM + c];
        }

        // smoothed[lane] = sum_i g[i] * v[lane + i - 3]; out-of-range -> 0
        // (idx & 31 wraps onto lanes >= 20 which hold v = 0)
        float sm;
        {
            float v0 = __shfl_sync(FULL, v, (lane - 3) & 31);
            float v1 = __shfl_sync(FULL, v, (lane - 2) & 31);
            float v2 = __shfl_sync(FULL, v, (lane - 1) & 31);
            float v3 = v;
            float v4 = __shfl_sync(FULL, v, (lane + 1) & 31);
            float v5 = __shfl_sync(FULL, v, (lane + 2) & 31);
            float v6 = __shfl_sync(FULL, v, (lane + 3) & 31);
            float v7 = __shfl_sync(FULL, v, (lane + 4) & 31);
            float v8 = __shfl_sync(FULL, v, (lane + 5) & 31);
            sm = G0 * v0;
            sm = fmaf(G1, v1, sm);
            sm = fmaf(G2, v2, sm);
            sm = fmaf(G3, v3, sm);
            sm = fmaf(G4, v4, sm);
            sm = fmaf(G3, v5, sm);
            sm = fmaf(G2, v6, sm);
            sm = fmaf(G1, v7, sm);
            sm = fmaf(G0, v8, sm);
        }

        float m = (lane < wlen && lane < WINC) ? sm : -INFINITY;
        #pragma unroll
        for (int o = 16; o; o >>= 1) m = fmaxf(m, __shfl_xor_sync(FULL, m, o));
        if (lane == 0) contrib += -m;
    }

    float tot = block_reduce_sum(contrib);
    if (tid == 0) atomicAdd(out, tot);     // RED.ADD.F32, no-return fast path
}

extern "C" void kernel_launch(void* const* d_in, const int* in_sizes, int n_in,
                              void* d_out, int out_size) {
    const float* X       = (const float*)d_in[0];
    const int*   lengths = (const int*)d_in[1];
    const int*   tgt     = (const int*)d_in[2];
    const int*   p_end   = (const int*)d_in[3];
    const int*   pnum    = (const int*)d_in[4];
    float*       out     = (float*)d_out;

    cudaMemsetAsync(out, 0, sizeof(float));          // graph-capturable memset node
    fused_kernel<<<NBLK, NTHR>>>(X, lengths, tgt, p_end, pnum, out);
}